// round 7
// baseline (speedup 1.0000x reference)
#include <cuda_runtime.h>
#include <math.h>

#define NN 8
#define CC 128
#define HH 96
#define WW 96
#define GG 8
#define GCH 16
#define HWSZ (HH*WW)            // 9216
#define NHW (NN*HWSZ)           // 73728
#define OMD 216
#define BNP 224                 // padded N for the GEMM
#define GN_EPS 1e-5f

// ---------------- device scratch ----------------
__device__ float g_x1[NHW * CC];      // dwconv+bias output, NHWC
__device__ float g_xnhwc[NHW * CC];   // input transposed to NHWC
__device__ float g_om[NHW * OMD];     // offsets/masks GEMM output
__device__ float g_omwT[CC * BNP];    // om_w transposed [k][n], zero-padded
__device__ float g_ombp[BNP];         // om_b zero-padded
__device__ float g_sum[NN];
__device__ float g_sumsq[NN];

// ---------------- f32x2 helpers ----------------
__device__ __forceinline__ unsigned long long pack2(float lo, float hi) {
    unsigned long long d;
    asm("mov.b64 %0, {%1, %2};" : "=l"(d) : "f"(lo), "f"(hi));
    return d;
}
__device__ __forceinline__ void unpack2(unsigned long long v, float& lo, float& hi) {
    asm("mov.b64 {%0, %1}, %2;" : "=f"(lo), "=f"(hi) : "l"(v));
}
__device__ __forceinline__ void fma2(unsigned long long& acc, unsigned long long a,
                                     unsigned long long b) {
    asm("fma.rn.f32x2 %0, %1, %2, %0;" : "+l"(acc) : "l"(a), "l"(b));
}

// ---------------- K0: prep (init stats + transpose om_w + pad bias) ----------------
__global__ __launch_bounds__(256) void k_prep(const float* __restrict__ om_w,
                                              const float* __restrict__ om_b) {
    int idx = blockIdx.x * 256 + threadIdx.x;
    if (idx < CC * BNP) {
        int k = idx / BNP;
        int n = idx - k * BNP;
        g_omwT[idx] = (n < OMD) ? om_w[n * CC + k] : 0.f;
    }
    if (idx < BNP) g_ombp[idx] = (idx < OMD) ? om_b[idx] : 0.f;
    if (idx < NN) { g_sum[idx] = 0.f; g_sumsq[idx] = 0.f; }
}

// ---------------- K1: smem-tiled depthwise conv + bias, NHWC transpose, stats --------
#define CST 305
#define RST 101
#define DW_SMEM ((32*CST + 32*97) * 4)
extern __shared__ float dsm[];
__global__ __launch_bounds__(256) void k_dwconv(const float* __restrict__ x,
                                                const float* __restrict__ dw_w,
                                                const float* __restrict__ dw_b) {
    float* s_in  = dsm;
    float* s_out = dsm + 32 * CST;
    __shared__ float rbuf[16];

    const int h  = blockIdx.x;
    const int cb = blockIdx.y;
    const int n  = blockIdx.z;
    const int tid = threadIdx.x;

    #pragma unroll
    for (int it = 0; it < 9; ++it) {
        int idx = tid + it * 256;
        int c = idx / 72;
        int rem = idx - c * 72;
        int r = rem / 24;
        int q = rem - r * 24;
        int y = h - 1 + r;
        float4 v = {0.f, 0.f, 0.f, 0.f};
        if ((unsigned)y < HH)
            v = *(const float4*)&x[((size_t)(n * CC + cb * 32 + c)) * HWSZ + y * WW + q * 4];
        float* d = &s_in[c * CST + r * RST + 1 + q * 4];
        d[0] = v.x; d[1] = v.y; d[2] = v.z; d[3] = v.w;
    }
    if (tid < 96) {
        int c = tid / 3, r = tid - c * 3;
        s_in[c * CST + r * RST + 0]  = 0.f;
        s_in[c * CST + r * RST + 97] = 0.f;
    }
    __syncthreads();

    const int c  = tid >> 3;
    const int w0 = (tid & 7) * 12;
    const int cg = cb * 32 + c;
    float wgt[9];
    #pragma unroll
    for (int t = 0; t < 9; ++t) wgt[t] = dw_w[cg * 9 + t];
    const float bias = dw_b[cg];
    const float* rowp = &s_in[c * CST];

    float s1 = 0.f, s2 = 0.f;
    #pragma unroll
    for (int i = 0; i < 12; ++i) {
        int w = w0 + i;
        float acc = bias;
        #pragma unroll
        for (int r = 0; r < 3; ++r)
            #pragma unroll
            for (int dx = 0; dx < 3; ++dx)
                acc = fmaf(rowp[r * RST + w + dx], wgt[r * 3 + dx], acc);
        s_out[c * 97 + w] = acc;
        s1 += acc;
        s2 += acc * acc;
    }

    #pragma unroll
    for (int o = 16; o; o >>= 1) {
        s1 += __shfl_down_sync(0xffffffffu, s1, o);
        s2 += __shfl_down_sync(0xffffffffu, s2, o);
    }
    int wid = tid >> 5, lane = tid & 31;
    if (lane == 0) { rbuf[wid] = s1; rbuf[8 + wid] = s2; }
    __syncthreads();
    if (tid == 0) {
        float a = 0.f, b = 0.f;
        #pragma unroll
        for (int i = 0; i < 8; ++i) { a += rbuf[i]; b += rbuf[8 + i]; }
        atomicAdd(&g_sum[n], a);
        atomicAdd(&g_sumsq[n], b);
    }

    size_t base = ((size_t)(n * HWSZ + h * WW)) * CC + cb * 32;
    for (int idx = tid; idx < 3072; idx += 256) {
        int ww = idx >> 5;
        int cc = idx & 31;
        g_x1   [base + (size_t)ww * CC + cc] = s_out[cc * 97 + ww];
        g_xnhwc[base + (size_t)ww * CC + cc] = s_in[cc * CST + RST + 1 + ww];
    }
}

// ---------------- K3: fused norm+GELU + GEMM via fma.rn.f32x2 ----------------
extern __shared__ float sm_g[];
__global__ __launch_bounds__(256, 1) void k_gemm(const float* __restrict__ gn_w,
                                                 const float* __restrict__ gn_b) {
    float* Bs = sm_g;                 // [128][BNP]
    float* As = sm_g + CC * BNP;      // [16][128]

    const int tid = threadIdx.x;
    const int bm  = blockIdx.x;
    const int tm  = tid & 31;
    const int tn  = tid >> 5;

    {
        const float4* src = (const float4*)g_omwT;
        float4* dst = (float4*)Bs;
        #pragma unroll
        for (int i = 0; i < CC * BNP / 4 / 256; ++i)
            dst[i * 256 + tid] = src[i * 256 + tid];
    }

    const int nidx = (bm * 128) / HWSZ;
    const float inv = 1.f / (float)(CC * HWSZ);
    const float mu = g_sum[nidx] * inv;
    const float rs = rsqrtf(g_sumsq[nidx] * inv - mu * mu + GN_EPS);

    unsigned long long acc[4][14];
    #pragma unroll
    for (int j = 0; j < 14; ++j) {
        unsigned long long bb = pack2(g_ombp[tn * 28 + 2 * j], g_ombp[tn * 28 + 2 * j + 1]);
        #pragma unroll
        for (int i = 0; i < 4; ++i) acc[i][j] = bb;
    }

    const int c0 = (tid & 3) * 4;
    const int rowb = tid >> 2;

    for (int kc = 0; kc < 8; ++kc) {
        #pragma unroll
        for (int pass = 0; pass < 2; ++pass) {
            int row = pass * 64 + rowb;
            int p = bm * 128 + row;
            float4 xv = *(const float4*)&g_x1[(size_t)p * CC + kc * 16 + c0];
            float vv[4] = {xv.x, xv.y, xv.z, xv.w};
            #pragma unroll
            for (int j = 0; j < 4; ++j) {
                int c = kc * 16 + c0 + j;
                float v = (vv[j] - mu) * rs * gn_w[c] + gn_b[c];
                v = 0.5f * v * (1.0f + erff(v * 0.7071067811865475f));
                As[(c0 + j) * 128 + row] = v;
            }
        }
        __syncthreads();
        #pragma unroll
        for (int kk = 0; kk < 16; ++kk) {
            float4 a4 = *(const float4*)&As[kk * 128 + tm * 4];
            unsigned long long a2[4];
            a2[0] = pack2(a4.x, a4.x);
            a2[1] = pack2(a4.y, a4.y);
            a2[2] = pack2(a4.z, a4.z);
            a2[3] = pack2(a4.w, a4.w);
            const unsigned long long* brow =
                (const unsigned long long*)&Bs[(kc * 16 + kk) * BNP + tn * 28];
            #pragma unroll
            for (int j = 0; j < 14; ++j) {
                unsigned long long b2 = brow[j];
                fma2(acc[0][j], a2[0], b2);
                fma2(acc[1][j], a2[1], b2);
                fma2(acc[2][j], a2[2], b2);
                fma2(acc[3][j], a2[3], b2);
            }
        }
        __syncthreads();
    }

    float* Ep = sm_g;
    #pragma unroll
    for (int i = 0; i < 4; ++i) {
        int row = tm * 4 + i;
        #pragma unroll
        for (int j = 0; j < 14; ++j) {
            float lo, hi;
            unpack2(acc[i][j], lo, hi);
            Ep[row * 227 + tn * 28 + 2 * j]     = lo;
            Ep[row * 227 + tn * 28 + 2 * j + 1] = hi;
        }
    }
    __syncthreads();
    for (int idx = tid; idx < 128 * OMD; idx += 256) {
        int r = idx / OMD;
        int col = idx - r * OMD;
        g_om[(size_t)(bm * 128 + r) * OMD + col] = Ep[r * 227 + col];
    }
}

// ---------------- K4: deformable sampling, 32-px blocks, thread=(pixel,group) ----------
#define SPX 32
#define TILEST 133
#define SAMP_SMEM ((SPX*220 + SPX*TILEST) * 4)   // 45184 B -> 4-5 blocks/SM
extern __shared__ float sm_s[];
__global__ __launch_bounds__(256, 4) void k_sample(float* __restrict__ out) {
    float* s_om = sm_s;                       // [SPX][220]
    float* tile = sm_s + SPX * 220;           // [SPX][TILEST]

    const int tid = threadIdx.x;
    const int p   = tid >> 3;                 // 0..31 pixel
    const int g   = tid & 7;                  // group
    const int pb  = blockIdx.x * SPX;
    const int pg  = pb + p;
    const int n   = pg / HWSZ;
    const int rem = pg - n * HWSZ;
    const int h   = rem / WW;
    const int w   = rem - h * WW;

    // stage om tile: SPX pixels x 216 floats (coalesced float4)
    {
        const float4* src = (const float4*)(g_om + (size_t)pb * OMD);
        for (int idx = tid; idx < SPX * 54; idx += 256) {
            int pix = idx / 54;
            int c4 = idx - pix * 54;
            *(float4*)&s_om[pix * 220 + c4 * 4] = src[pix * 54 + c4];
        }
    }
    __syncthreads();

    const float* xb  = g_xnhwc + (size_t)n * HWSZ * CC;
    const float* omr = &s_om[p * 220 + g * 27];
    const int cbase  = g * GCH;

    float acc[16];
    #pragma unroll
    for (int i = 0; i < 16; ++i) acc[i] = 0.f;

    #pragma unroll
    for (int k = 0; k < 9; ++k) {
        float offx = omr[2 * k];
        float offy = omr[2 * k + 1];
        float m    = omr[18 + k];
        float ly = (float)(h + (k / 3) - 1) + offy;
        float lx = (float)(w + (k % 3) - 1) + offx;
        float y0f = floorf(ly), x0f = floorf(lx);
        float fy = ly - y0f, fx = lx - x0f;
        int y0 = (int)y0f, x0 = (int)x0f;
        float wts[4];
        wts[0] = (1.f - fy) * (1.f - fx) * m;
        wts[1] = (1.f - fy) * fx * m;
        wts[2] = fy * (1.f - fx) * m;
        wts[3] = fy * fx * m;
        #pragma unroll
        for (int t = 0; t < 4; ++t) {
            int yy = y0 + (t >> 1);
            int xx = x0 + (t & 1);
            if ((unsigned)yy < HH && (unsigned)xx < WW) {
                float wt = wts[t];
                const float* src = &xb[(size_t)(yy * WW + xx) * CC + cbase];
                #pragma unroll
                for (int q = 0; q < 4; ++q) {
                    float4 v = *(const float4*)(src + 4 * q);
                    acc[4*q+0] = fmaf(wt, v.x, acc[4*q+0]);
                    acc[4*q+1] = fmaf(wt, v.y, acc[4*q+1]);
                    acc[4*q+2] = fmaf(wt, v.z, acc[4*q+2]);
                    acc[4*q+3] = fmaf(wt, v.w, acc[4*q+3]);
                }
            }
        }
    }
    {
        float* trow = &tile[p * TILEST + cbase];
        #pragma unroll
        for (int i = 0; i < 16; ++i) trow[i] = acc[i];   // scalar STS (odd stride)
    }
    __syncthreads();

    // coalesced NCHW writeout: 128 ch x 32 pixels
    const int hw0 = pb - n * HWSZ;
    float* ob = out + (size_t)n * CC * HWSZ + hw0;
    for (int idx = tid; idx < CC * SPX; idx += 256) {
        int c = idx >> 5;
        int pp = idx & 31;
        ob[(size_t)c * HWSZ + pp] = tile[pp * TILEST + c];
    }
}

// ---------------- launcher ----------------
extern "C" void kernel_launch(void* const* d_in, const int* in_sizes, int n_in,
                              void* d_out, int out_size) {
    const float* x    = (const float*)d_in[0];
    const float* dw_w = (const float*)d_in[1];
    const float* dw_b = (const float*)d_in[2];
    const float* gn_w = (const float*)d_in[3];
    const float* gn_b = (const float*)d_in[4];
    const float* om_w = (const float*)d_in[5];
    const float* om_b = (const float*)d_in[6];
    float* out = (float*)d_out;

    const int smem_gemm = (CC * BNP + 16 * CC) * sizeof(float);
    cudaFuncSetAttribute(k_dwconv, cudaFuncAttributeMaxDynamicSharedMemorySize, DW_SMEM);
    cudaFuncSetAttribute(k_gemm, cudaFuncAttributeMaxDynamicSharedMemorySize, smem_gemm);
    cudaFuncSetAttribute(k_sample, cudaFuncAttributeMaxDynamicSharedMemorySize, SAMP_SMEM);

    k_prep<<<(CC * BNP + 255) / 256, 256>>>(om_w, om_b);
    dim3 g1(HH, CC / 32, NN);
    k_dwconv<<<g1, 256, DW_SMEM>>>(x, dw_w, dw_b);
    k_gemm<<<NHW / 128, 256, smem_gemm>>>(gn_w, gn_b);
    k_sample<<<NHW / SPX, 256, SAMP_SMEM>>>(out);
}

// round 8
// speedup vs baseline: 1.4007x; 1.4007x over previous
#include <cuda_runtime.h>
#include <math.h>

#define NN 8
#define CC 128
#define HH 96
#define WW 96
#define GG 8
#define GCH 16
#define HWSZ (HH*WW)            // 9216
#define NHW (NN*HWSZ)           // 73728
#define OMD 216
#define BNP 224                 // padded N for the GEMM
#define GN_EPS 1e-5f

// ---------------- device scratch ----------------
__device__ float g_x1[NHW * CC];      // dwconv+bias output, NHWC
__device__ float g_xnhwc[NHW * CC];   // input transposed to NHWC
__device__ float g_om[NHW * OMD];     // offsets/masks GEMM output
__device__ float g_omwT[CC * BNP];    // om_w transposed [k][n], zero-padded
__device__ float g_ombp[BNP];         // om_b zero-padded
__device__ float g_sum[NN];
__device__ float g_sumsq[NN];

// ---------------- f32x2 helpers ----------------
__device__ __forceinline__ unsigned long long pack2(float lo, float hi) {
    unsigned long long d;
    asm("mov.b64 %0, {%1, %2};" : "=l"(d) : "f"(lo), "f"(hi));
    return d;
}
__device__ __forceinline__ void unpack2(unsigned long long v, float& lo, float& hi) {
    asm("mov.b64 {%0, %1}, %2;" : "=f"(lo), "=f"(hi) : "l"(v));
}
__device__ __forceinline__ void fma2(unsigned long long& acc, unsigned long long a,
                                     unsigned long long b) {
    asm("fma.rn.f32x2 %0, %1, %2, %0;" : "+l"(acc) : "l"(a), "l"(b));
}

// ---------------- K0: prep (init stats + transpose om_w + pad bias) ----------------
__global__ __launch_bounds__(256) void k_prep(const float* __restrict__ om_w,
                                              const float* __restrict__ om_b) {
    int idx = blockIdx.x * 256 + threadIdx.x;
    if (idx < CC * BNP) {
        int k = idx / BNP;
        int n = idx - k * BNP;
        g_omwT[idx] = (n < OMD) ? om_w[n * CC + k] : 0.f;
    }
    if (idx < BNP) g_ombp[idx] = (idx < OMD) ? om_b[idx] : 0.f;
    if (idx < NN) { g_sum[idx] = 0.f; g_sumsq[idx] = 0.f; }
}

// ---------------- K1: smem-tiled depthwise conv + bias, NHWC transpose, stats --------
#define CST 305
#define RST 101
#define DW_SMEM ((32*CST + 32*97) * 4)
extern __shared__ float dsm[];
__global__ __launch_bounds__(256) void k_dwconv(const float* __restrict__ x,
                                                const float* __restrict__ dw_w,
                                                const float* __restrict__ dw_b) {
    float* s_in  = dsm;
    float* s_out = dsm + 32 * CST;
    __shared__ float rbuf[16];

    const int h  = blockIdx.x;
    const int cb = blockIdx.y;
    const int n  = blockIdx.z;
    const int tid = threadIdx.x;

    #pragma unroll
    for (int it = 0; it < 9; ++it) {
        int idx = tid + it * 256;
        int c = idx / 72;
        int rem = idx - c * 72;
        int r = rem / 24;
        int q = rem - r * 24;
        int y = h - 1 + r;
        float4 v = {0.f, 0.f, 0.f, 0.f};
        if ((unsigned)y < HH)
            v = *(const float4*)&x[((size_t)(n * CC + cb * 32 + c)) * HWSZ + y * WW + q * 4];
        float* d = &s_in[c * CST + r * RST + 1 + q * 4];
        d[0] = v.x; d[1] = v.y; d[2] = v.z; d[3] = v.w;
    }
    if (tid < 96) {
        int c = tid / 3, r = tid - c * 3;
        s_in[c * CST + r * RST + 0]  = 0.f;
        s_in[c * CST + r * RST + 97] = 0.f;
    }
    __syncthreads();

    const int c  = tid >> 3;
    const int w0 = (tid & 7) * 12;
    const int cg = cb * 32 + c;
    float wgt[9];
    #pragma unroll
    for (int t = 0; t < 9; ++t) wgt[t] = dw_w[cg * 9 + t];
    const float bias = dw_b[cg];
    const float* rowp = &s_in[c * CST];

    float s1 = 0.f, s2 = 0.f;
    #pragma unroll
    for (int i = 0; i < 12; ++i) {
        int w = w0 + i;
        float acc = bias;
        #pragma unroll
        for (int r = 0; r < 3; ++r)
            #pragma unroll
            for (int dx = 0; dx < 3; ++dx)
                acc = fmaf(rowp[r * RST + w + dx], wgt[r * 3 + dx], acc);
        s_out[c * 97 + w] = acc;
        s1 += acc;
        s2 += acc * acc;
    }

    #pragma unroll
    for (int o = 16; o; o >>= 1) {
        s1 += __shfl_down_sync(0xffffffffu, s1, o);
        s2 += __shfl_down_sync(0xffffffffu, s2, o);
    }
    int wid = tid >> 5, lane = tid & 31;
    if (lane == 0) { rbuf[wid] = s1; rbuf[8 + wid] = s2; }
    __syncthreads();
    if (tid == 0) {
        float a = 0.f, b = 0.f;
        #pragma unroll
        for (int i = 0; i < 8; ++i) { a += rbuf[i]; b += rbuf[8 + i]; }
        atomicAdd(&g_sum[n], a);
        atomicAdd(&g_sumsq[n], b);
    }

    size_t base = ((size_t)(n * HWSZ + h * WW)) * CC + cb * 32;
    for (int idx = tid; idx < 3072; idx += 256) {
        int ww = idx >> 5;
        int cc = idx & 31;
        g_x1   [base + (size_t)ww * CC + cc] = s_out[cc * 97 + ww];
        g_xnhwc[base + (size_t)ww * CC + cc] = s_in[cc * CST + RST + 1 + ww];
    }
}

// ---------------- K3: fused norm+GELU + GEMM via fma.rn.f32x2 ----------------
extern __shared__ float sm_g[];
__global__ __launch_bounds__(256, 1) void k_gemm(const float* __restrict__ gn_w,
                                                 const float* __restrict__ gn_b) {
    float* Bs = sm_g;                 // [128][BNP]
    float* As = sm_g + CC * BNP;      // [16][128]

    const int tid = threadIdx.x;
    const int bm  = blockIdx.x;
    const int tm  = tid & 31;
    const int tn  = tid >> 5;

    {
        const float4* src = (const float4*)g_omwT;
        float4* dst = (float4*)Bs;
        #pragma unroll
        for (int i = 0; i < CC * BNP / 4 / 256; ++i)
            dst[i * 256 + tid] = src[i * 256 + tid];
    }

    const int nidx = (bm * 128) / HWSZ;
    const float inv = 1.f / (float)(CC * HWSZ);
    const float mu = g_sum[nidx] * inv;
    const float rs = rsqrtf(g_sumsq[nidx] * inv - mu * mu + GN_EPS);

    unsigned long long acc[4][14];
    #pragma unroll
    for (int j = 0; j < 14; ++j) {
        unsigned long long bb = pack2(g_ombp[tn * 28 + 2 * j], g_ombp[tn * 28 + 2 * j + 1]);
        #pragma unroll
        for (int i = 0; i < 4; ++i) acc[i][j] = bb;
    }

    const int c0 = (tid & 3) * 4;
    const int rowb = tid >> 2;

    for (int kc = 0; kc < 8; ++kc) {
        #pragma unroll
        for (int pass = 0; pass < 2; ++pass) {
            int row = pass * 64 + rowb;
            int p = bm * 128 + row;
            float4 xv = *(const float4*)&g_x1[(size_t)p * CC + kc * 16 + c0];
            float vv[4] = {xv.x, xv.y, xv.z, xv.w};
            #pragma unroll
            for (int j = 0; j < 4; ++j) {
                int c = kc * 16 + c0 + j;
                float v = (vv[j] - mu) * rs * gn_w[c] + gn_b[c];
                v = 0.5f * v * (1.0f + erff(v * 0.7071067811865475f));
                As[(c0 + j) * 128 + row] = v;
            }
        }
        __syncthreads();
        #pragma unroll
        for (int kk = 0; kk < 16; ++kk) {
            float4 a4 = *(const float4*)&As[kk * 128 + tm * 4];
            unsigned long long a2[4];
            a2[0] = pack2(a4.x, a4.x);
            a2[1] = pack2(a4.y, a4.y);
            a2[2] = pack2(a4.z, a4.z);
            a2[3] = pack2(a4.w, a4.w);
            const unsigned long long* brow =
                (const unsigned long long*)&Bs[(kc * 16 + kk) * BNP + tn * 28];
            #pragma unroll
            for (int j = 0; j < 14; ++j) {
                unsigned long long b2 = brow[j];
                fma2(acc[0][j], a2[0], b2);
                fma2(acc[1][j], a2[1], b2);
                fma2(acc[2][j], a2[2], b2);
                fma2(acc[3][j], a2[3], b2);
            }
        }
        __syncthreads();
    }

    float* Ep = sm_g;
    #pragma unroll
    for (int i = 0; i < 4; ++i) {
        int row = tm * 4 + i;
        #pragma unroll
        for (int j = 0; j < 14; ++j) {
            float lo, hi;
            unpack2(acc[i][j], lo, hi);
            Ep[row * 227 + tn * 28 + 2 * j]     = lo;
            Ep[row * 227 + tn * 28 + 2 * j + 1] = hi;
        }
    }
    __syncthreads();
    for (int idx = tid; idx < 128 * OMD; idx += 256) {
        int r = idx / OMD;
        int col = idx - r * OMD;
        g_om[(size_t)(bm * 128 + r) * OMD + col] = Ep[r * 227 + col];
    }
}

// ---------------- K4: deformable sampling (R5 mapping, smem tile only) ----------------
// grid 1152, block 256. 64 pixels/block; om read directly from gmem (L1-resident).
#define TILEST 133
#define SAMP_SMEM (64 * TILEST * 4)     // 34048 B -> 5-6 blocks/SM
extern __shared__ float sm_s[];
__global__ __launch_bounds__(256) void k_sample(float* __restrict__ out) {
    float (*tile)[TILEST] = (float(*)[TILEST])sm_s;

    const int tid = threadIdx.x;
    const int gidx = tid >> 2;       // 0..63 pixel in block
    const int l = tid & 3;           // channel quad
    const int pb = blockIdx.x * 64;
    const int p = pb + gidx;
    const int n = p / HWSZ;
    const int rem = p - n * HWSZ;
    const int h = rem / WW;
    const int w = rem - h * WW;

    const float* xb = g_xnhwc + (size_t)n * HWSZ * CC;
    const float* omr0 = g_om + (size_t)p * OMD;

    for (int g = 0; g < GG; ++g) {
        const float* omr = omr0 + g * 27;
        const int cbase = g * GCH + l * 4;
        float ax = 0.f, ay = 0.f, az = 0.f, aw = 0.f;
        #pragma unroll
        for (int k = 0; k < 9; ++k) {
            float offx = __ldg(omr + 2 * k);
            float offy = __ldg(omr + 2 * k + 1);
            float m    = __ldg(omr + 18 + k);
            float ly = (float)(h + (k / 3) - 1) + offy;
            float lx = (float)(w + (k % 3) - 1) + offx;
            float y0f = floorf(ly), x0f = floorf(lx);
            float fy = ly - y0f, fx = lx - x0f;
            int y0 = (int)y0f, x0 = (int)x0f;
            float w00 = (1.f - fy) * (1.f - fx) * m;
            float w01 = (1.f - fy) * fx * m;
            float w10 = fy * (1.f - fx) * m;
            float w11 = fy * fx * m;
            #pragma unroll
            for (int t = 0; t < 4; ++t) {
                int yy = y0 + (t >> 1);
                int xx = x0 + (t & 1);
                float wt = (t == 0) ? w00 : (t == 1) ? w01 : (t == 2) ? w10 : w11;
                if ((unsigned)yy < HH && (unsigned)xx < WW) {
                    const float4 v = *(const float4*)&xb[(size_t)((yy * WW + xx)) * CC + cbase];
                    ax = fmaf(wt, v.x, ax);
                    ay = fmaf(wt, v.y, ay);
                    az = fmaf(wt, v.z, az);
                    aw = fmaf(wt, v.w, aw);
                }
            }
        }
        tile[gidx][cbase + 0] = ax;
        tile[gidx][cbase + 1] = ay;
        tile[gidx][cbase + 2] = az;
        tile[gidx][cbase + 3] = aw;
    }
    __syncthreads();

    // coalesced NCHW writeout: 128 ch x 64 pixels
    const int hw0 = pb - n * HWSZ;
    float* ob = out + (size_t)n * CC * HWSZ;
    for (int idx = tid; idx < 8192; idx += 256) {
        int c = idx >> 6;
        int pp = idx & 63;
        ob[(size_t)c * HWSZ + hw0 + pp] = tile[pp][c];
    }
}

// ---------------- launcher ----------------
extern "C" void kernel_launch(void* const* d_in, const int* in_sizes, int n_in,
                              void* d_out, int out_size) {
    const float* x    = (const float*)d_in[0];
    const float* dw_w = (const float*)d_in[1];
    const float* dw_b = (const float*)d_in[2];
    const float* gn_w = (const float*)d_in[3];
    const float* gn_b = (const float*)d_in[4];
    const float* om_w = (const float*)d_in[5];
    const float* om_b = (const float*)d_in[6];
    float* out = (float*)d_out;

    const int smem_gemm = (CC * BNP + 16 * CC) * sizeof(float);
    cudaFuncSetAttribute(k_dwconv, cudaFuncAttributeMaxDynamicSharedMemorySize, DW_SMEM);
    cudaFuncSetAttribute(k_gemm, cudaFuncAttributeMaxDynamicSharedMemorySize, smem_gemm);
    cudaFuncSetAttribute(k_sample, cudaFuncAttributeMaxDynamicSharedMemorySize, SAMP_SMEM);

    k_prep<<<(CC * BNP + 255) / 256, 256>>>(om_w, om_b);
    dim3 g1(HH, CC / 32, NN);
    k_dwconv<<<g1, 256, DW_SMEM>>>(x, dw_w, dw_b);
    k_gemm<<<NHW / 128, 256, smem_gemm>>>(gn_w, gn_b);
    k_sample<<<NHW / 64, 256, SAMP_SMEM>>>(out);
}